// round 14
// baseline (speedup 1.0000x reference)
#include <cuda_runtime.h>

#define NN 50000
#define NE 600000
#define D  128

// ---------------- scratch (device globals; no allocation allowed) -------------
__device__ float g_mean[NN * D];
__device__ float g_hA[NN * D];
__device__ float g_hB[NN * D];
__device__ int   g_deg[NN];
__device__ float g_inv[NN];
__device__ int   g_ptr[NN + 1];
__device__ int   g_cur[NN];
__device__ int   g_csrc[NE];
__device__ int   g_bsum[128];
__device__ int   g_boff[128];
__device__ int   g_is64;

// ---------------- edge_index dtype detection ----------------------------------
// int64 ids < 50000 => every odd 32-bit word is 0. int32 ids => odd words are
// node ids; 256 of them all being zero has probability ~0. Deterministic.
__global__ void k_detect(const int* __restrict__ ei) {
    __shared__ int s[256];
    int t = threadIdx.x;
    s[t] = ei[2 * t + 1];
    __syncthreads();
    for (int off = 128; off > 0; off >>= 1) {
        if (t < off) s[t] |= s[t + off];
        __syncthreads();
    }
    if (t == 0) g_is64 = (s[0] == 0) ? 1 : 0;
}

__device__ __forceinline__ int edge_src(const int* ei, int e) {
    return g_is64 ? (int)((const long long*)ei)[e] : ei[e];
}
__device__ __forceinline__ int edge_dst(const int* ei, int e) {
    return g_is64 ? (int)((const long long*)ei)[NE + e] : ei[NE + e];
}

// ---------------- CSR build ---------------------------------------------------
__global__ void k_zero_deg() {
    int i = blockIdx.x * blockDim.x + threadIdx.x;
    if (i < NN) g_deg[i] = 0;
}

__global__ void k_deg(const int* __restrict__ ei) {
    int e = blockIdx.x * blockDim.x + threadIdx.x;
    if (e < NE) {
        int d = edge_dst(ei, e);
        if (d >= 0 && d < NN) atomicAdd(&g_deg[d], 1);
    }
}

// block-local inclusive scan (512 wide), writes block-local exclusive ptr + block sums
__global__ void k_scan1() {
    __shared__ int s[512];
    int tid = threadIdx.x;
    int i = blockIdx.x * 512 + tid;
    int v = (i < NN) ? g_deg[i] : 0;
    s[tid] = v;
    __syncthreads();
    for (int off = 1; off < 512; off <<= 1) {
        int t = (tid >= off) ? s[tid - off] : 0;
        __syncthreads();
        s[tid] += t;
        __syncthreads();
    }
    int incl = s[tid];
    if (i < NN) {
        g_ptr[i] = incl - v;           // block-local exclusive
        g_inv[i] = 1.0f / (float)max(v, 1);
    }
    if (tid == 511) g_bsum[blockIdx.x] = incl;
}

__global__ void k_scan2(int nb) {
    if (threadIdx.x == 0) {
        int run = 0;
        for (int b = 0; b < nb; b++) { g_boff[b] = run; run += g_bsum[b]; }
        g_ptr[NN] = run;
    }
}

__global__ void k_scan3() {
    int i = blockIdx.x * 512 + threadIdx.x;
    if (i < NN) {
        int p = g_ptr[i] + g_boff[i >> 9];
        g_ptr[i] = p;
        g_cur[i] = p;
    }
}

__global__ void k_fill(const int* __restrict__ ei) {
    int e = blockIdx.x * blockDim.x + threadIdx.x;
    if (e < NE) {
        int s = edge_src(ei, e);
        int d = edge_dst(ei, e);
        if (d >= 0 && d < NN && s >= 0 && s < NN) {
            int pos = atomicAdd(&g_cur[d], 1);
            g_csrc[pos] = s;
        }
    }
}

// ---------------- mean aggregation: warp per node, float4 per lane ------------
// layer: 0 -> read x (param), 1 -> read g_hA, 2 -> read g_hB. Writes g_mean.
__global__ void k_aggr(const float* __restrict__ x, int layer) {
    int w = (blockIdx.x * blockDim.x + threadIdx.x) >> 5;
    int lane = threadIdx.x & 31;
    if (w >= NN) return;
    const float* feat = (layer == 0) ? x : (layer == 1) ? g_hA : g_hB;
    int beg = g_ptr[w], end = g_ptr[w + 1];
    const float4* f4 = (const float4*)feat;
    float4 acc = make_float4(0.f, 0.f, 0.f, 0.f);
    #pragma unroll 2
    for (int e = beg; e < end; e++) {
        int s = g_csrc[e];
        float4 v = f4[s * 32 + lane];
        acc.x += v.x; acc.y += v.y; acc.z += v.z; acc.w += v.w;
    }
    float inv = g_inv[w];
    acc.x *= inv; acc.y *= inv; acc.z *= inv; acc.w *= inv;
    ((float4*)g_mean)[w * 32 + lane] = acc;
}

// ---------------- fused dual-GEMM + bias + relu -------------------------------
// out[i][j] = relu( sum_k mean[i][k]*Wl[j][k] + sum_k feat[i][k]*Wr[j][k] + bl[j] )
// layer selects feat input (0=x param,1=g_hA,2=g_hB) and output (0->g_hA,1->g_hB,2->dout).
// Tile: 64 rows x 128 cols per block; 256 threads; thread tile 4x8.
#define TR 64
#define SWS 132
#define SAS 264
#define GEMM_SMEM ((256 * SWS + TR * SAS) * 4)

__global__ void __launch_bounds__(256, 1)
k_gemm(const float* __restrict__ x,
       const float* __restrict__ Wl, const float* __restrict__ bl,
       const float* __restrict__ Wr, float* __restrict__ dout, int layer) {
    extern __shared__ float sm[];
    float* sW = sm;                 // 256 x SWS
    float* sA = sm + 256 * SWS;     // TR x SAS
    int tid = threadIdx.x;
    int row0 = blockIdx.x * TR;

    const float* feat = (layer == 0) ? x : (layer == 1) ? g_hA : g_hB;
    float* out = (layer == 0) ? g_hA : (layer == 1) ? g_hB : dout;

    // load both weights transposed into smem: sW[k_global][j] = W[j][k]
    for (int idx = tid; idx < 2 * D * D; idx += 256) {
        int m = idx >> 14;              // 0 -> Wl, 1 -> Wr
        int r = (idx >> 7) & 127;       // output row j
        int c = idx & 127;              // k
        float v = m ? Wr[r * D + c] : Wl[r * D + c];
        sW[(c + (m << 7)) * SWS + r] = v;
    }

    // load A tile rows: cols [0..127]=mean, [128..255]=feat
    for (int idx = tid; idx < TR * 64; idx += 256) {
        int r = idx >> 6;
        int q = idx & 63;
        int grow = row0 + r;
        float4 v = make_float4(0.f, 0.f, 0.f, 0.f);
        int cq = q & 31;
        if (grow < NN) {
            v = (q < 32) ? ((const float4*)g_mean)[grow * 32 + cq]
                         : ((const float4*)feat)[grow * 32 + cq];
        }
        *(float4*)&sA[r * SAS + ((q < 32) ? 0 : 128) + (cq << 2)] = v;
    }
    __syncthreads();

    int tx = tid & 15;   // col group: cols tx*8 .. tx*8+7
    int ty = tid >> 4;   // row group: rows ty*4 .. ty*4+3
    float acc[4][8];
    #pragma unroll
    for (int r = 0; r < 4; r++)
        #pragma unroll
        for (int c = 0; c < 8; c++) acc[r][c] = 0.f;

    const float* pA = &sA[ty * 4 * SAS];
    #pragma unroll 4
    for (int k = 0; k < 2 * D; k++) {
        float4 w0 = *(const float4*)&sW[k * SWS + tx * 8];
        float4 w1 = *(const float4*)&sW[k * SWS + tx * 8 + 4];
        float av[4];
        av[0] = pA[k];
        av[1] = pA[SAS + k];
        av[2] = pA[2 * SAS + k];
        av[3] = pA[3 * SAS + k];
        float wv[8] = {w0.x, w0.y, w0.z, w0.w, w1.x, w1.y, w1.z, w1.w};
        #pragma unroll
        for (int r = 0; r < 4; r++)
            #pragma unroll
            for (int c = 0; c < 8; c++)
                acc[r][c] += av[r] * wv[c];
    }

    float b[8];
    #pragma unroll
    for (int c = 0; c < 8; c++) b[c] = bl[tx * 8 + c];

    #pragma unroll
    for (int r = 0; r < 4; r++) {
        int grow = row0 + ty * 4 + r;
        if (grow < NN) {
            float4 o0, o1;
            o0.x = fmaxf(acc[r][0] + b[0], 0.f);
            o0.y = fmaxf(acc[r][1] + b[1], 0.f);
            o0.z = fmaxf(acc[r][2] + b[2], 0.f);
            o0.w = fmaxf(acc[r][3] + b[3], 0.f);
            o1.x = fmaxf(acc[r][4] + b[4], 0.f);
            o1.y = fmaxf(acc[r][5] + b[5], 0.f);
            o1.z = fmaxf(acc[r][6] + b[6], 0.f);
            o1.w = fmaxf(acc[r][7] + b[7], 0.f);
            *(float4*)&out[grow * D + tx * 8] = o0;
            *(float4*)&out[grow * D + tx * 8 + 4] = o1;
        }
    }
}

// ---------------- launch -------------------------------------------------------
extern "C" void kernel_launch(void* const* d_in, const int* in_sizes, int n_in,
                              void* d_out, int out_size) {
    const float* x  = (const float*)d_in[0];
    const int*   ei = (const int*)d_in[1];   // dtype resolved on-device (g_is64)
    const float* Wl1 = (const float*)d_in[2];
    const float* bl1 = (const float*)d_in[3];
    const float* Wr1 = (const float*)d_in[4];
    const float* Wl2 = (const float*)d_in[5];
    const float* bl2 = (const float*)d_in[6];
    const float* Wr2 = (const float*)d_in[7];
    const float* Wl3 = (const float*)d_in[8];
    const float* bl3 = (const float*)d_in[9];
    const float* Wr3 = (const float*)d_in[10];
    float* out = (float*)d_out;

    cudaFuncSetAttribute(k_gemm, cudaFuncAttributeMaxDynamicSharedMemorySize, GEMM_SMEM);

    const int nb = (NN + 511) / 512;           // 98 scan blocks
    const int eb = (NE + 255) / 256;
    const int gemm_blocks = (NN + TR - 1) / TR;
    const int aggr_blocks = (NN * 32 + 255) / 256;

    // CSR build (graph is identical every call; rebuilt each call for determinism rules)
    k_detect<<<1, 256>>>(ei);
    k_zero_deg<<<(NN + 255) / 256, 256>>>();
    k_deg<<<eb, 256>>>(ei);
    k_scan1<<<nb, 512>>>();
    k_scan2<<<1, 32>>>(nb);
    k_scan3<<<nb, 512>>>();
    k_fill<<<eb, 256>>>(ei);

    // layer 1: feat=x -> g_hA
    k_aggr<<<aggr_blocks, 256>>>(x, 0);
    k_gemm<<<gemm_blocks, 256, GEMM_SMEM>>>(x, Wl1, bl1, Wr1, out, 0);
    // layer 2: feat=g_hA -> g_hB
    k_aggr<<<aggr_blocks, 256>>>(x, 1);
    k_gemm<<<gemm_blocks, 256, GEMM_SMEM>>>(x, Wl2, bl2, Wr2, out, 1);
    // layer 3: feat=g_hB -> out
    k_aggr<<<aggr_blocks, 256>>>(x, 2);
    k_gemm<<<gemm_blocks, 256, GEMM_SMEM>>>(x, Wl3, bl3, Wr3, out, 2);
}

// round 17
// speedup vs baseline: 1.0232x; 1.0232x over previous
#include <cuda_runtime.h>
#include <cstdint>

#define NN 50000
#define NE 600000
#define D  128

// ---------------- scratch (device globals; no allocation allowed) -------------
__device__ float g_mean[NN * D];
__device__ float g_hA[NN * D];
__device__ float g_hB[NN * D];
__device__ int   g_deg[NN];
__device__ float g_inv[NN];
__device__ int   g_ptr[NN + 1];
__device__ int   g_cur[NN];
__device__ int   g_csrc[NE];
__device__ int   g_bsum[128];
__device__ int   g_boff[128];
__device__ int   g_is64;

// ---------------- edge_index dtype detection ----------------------------------
__global__ void k_detect(const int* __restrict__ ei) {
    __shared__ int s[256];
    int t = threadIdx.x;
    s[t] = ei[2 * t + 1];
    __syncthreads();
    for (int off = 128; off > 0; off >>= 1) {
        if (t < off) s[t] |= s[t + off];
        __syncthreads();
    }
    if (t == 0) g_is64 = (s[0] == 0) ? 1 : 0;
}

__device__ __forceinline__ int edge_src(const int* ei, int e) {
    return g_is64 ? (int)((const long long*)ei)[e] : ei[e];
}
__device__ __forceinline__ int edge_dst(const int* ei, int e) {
    return g_is64 ? (int)((const long long*)ei)[NE + e] : ei[NE + e];
}

// ---------------- CSR build ---------------------------------------------------
__global__ void k_zero_deg() {
    int i = blockIdx.x * blockDim.x + threadIdx.x;
    if (i < NN) g_deg[i] = 0;
}

__global__ void k_deg(const int* __restrict__ ei) {
    int e = blockIdx.x * blockDim.x + threadIdx.x;
    if (e < NE) {
        int d = edge_dst(ei, e);
        if (d >= 0 && d < NN) atomicAdd(&g_deg[d], 1);
    }
}

__global__ void k_scan1() {
    __shared__ int s[512];
    int tid = threadIdx.x;
    int i = blockIdx.x * 512 + tid;
    int v = (i < NN) ? g_deg[i] : 0;
    s[tid] = v;
    __syncthreads();
    for (int off = 1; off < 512; off <<= 1) {
        int t = (tid >= off) ? s[tid - off] : 0;
        __syncthreads();
        s[tid] += t;
        __syncthreads();
    }
    int incl = s[tid];
    if (i < NN) {
        g_ptr[i] = incl - v;
        g_inv[i] = 1.0f / (float)max(v, 1);
    }
    if (tid == 511) g_bsum[blockIdx.x] = incl;
}

__global__ void k_scan2(int nb) {
    if (threadIdx.x == 0) {
        int run = 0;
        for (int b = 0; b < nb; b++) { g_boff[b] = run; run += g_bsum[b]; }
        g_ptr[NN] = run;
    }
}

__global__ void k_scan3() {
    int i = blockIdx.x * 512 + threadIdx.x;
    if (i < NN) {
        int p = g_ptr[i] + g_boff[i >> 9];
        g_ptr[i] = p;
        g_cur[i] = p;
    }
}

__global__ void k_fill(const int* __restrict__ ei) {
    int e = blockIdx.x * blockDim.x + threadIdx.x;
    if (e < NE) {
        int s = edge_src(ei, e);
        int d = edge_dst(ei, e);
        if (d >= 0 && d < NN && s >= 0 && s < NN) {
            int pos = atomicAdd(&g_cur[d], 1);
            g_csrc[pos] = s;
        }
    }
}

// ---------------- mean aggregation: warp per node, float4 per lane ------------
__global__ void k_aggr(const float* __restrict__ x, int layer) {
    int w = (blockIdx.x * blockDim.x + threadIdx.x) >> 5;
    int lane = threadIdx.x & 31;
    if (w >= NN) return;
    const float* feat = (layer == 0) ? x : (layer == 1) ? g_hA : g_hB;
    int beg = g_ptr[w], end = g_ptr[w + 1];
    const float4* f4 = (const float4*)feat;
    float4 acc = make_float4(0.f, 0.f, 0.f, 0.f);
    #pragma unroll 2
    for (int e = beg; e < end; e++) {
        int s = g_csrc[e];
        float4 v = f4[s * 32 + lane];
        acc.x += v.x; acc.y += v.y; acc.z += v.z; acc.w += v.w;
    }
    float inv = g_inv[w];
    acc.x *= inv; acc.y *= inv; acc.z *= inv; acc.w *= inv;
    ((float4*)g_mean)[w * 32 + lane] = acc;
}

// ---------------- fused dual-GEMM + bias + relu (packed f32x2 mainloop) -------
// out[i][j] = relu( sum_k mean[i][k]*Wl[j][k] + sum_k feat[i][k]*Wr[j][k] + bl[j] )
// Tile: 64 rows x 128 cols per block; 256 threads; thread tile 4x8 (as 4x4 f32x2).
#define TR 64
#define SWS 132
#define SAS 264
#define GEMM_SMEM ((256 * SWS + TR * SAS) * 4)

__global__ void __launch_bounds__(256, 1)
k_gemm(const float* __restrict__ x,
       const float* __restrict__ Wl, const float* __restrict__ bl,
       const float* __restrict__ Wr, float* __restrict__ dout, int layer) {
    extern __shared__ float sm[];
    float* sW = sm;                 // 256 x SWS
    float* sA = sm + 256 * SWS;     // TR x SAS
    int tid = threadIdx.x;
    int row0 = blockIdx.x * TR;

    const float* feat = (layer == 0) ? x : (layer == 1) ? g_hA : g_hB;
    float* out = (layer == 0) ? g_hA : (layer == 1) ? g_hB : dout;

    // load both weights transposed into smem: sW[k_global][j] = W[j][k]
    for (int idx = tid; idx < 2 * D * D; idx += 256) {
        int m = idx >> 14;              // 0 -> Wl, 1 -> Wr
        int r = (idx >> 7) & 127;       // output row j
        int c = idx & 127;              // k
        float v = m ? Wr[r * D + c] : Wl[r * D + c];
        sW[(c + (m << 7)) * SWS + r] = v;
    }

    // load A tile rows: cols [0..127]=mean, [128..255]=feat
    for (int idx = tid; idx < TR * 64; idx += 256) {
        int r = idx >> 6;
        int q = idx & 63;
        int grow = row0 + r;
        float4 v = make_float4(0.f, 0.f, 0.f, 0.f);
        int cq = q & 31;
        if (grow < NN) {
            v = (q < 32) ? ((const float4*)g_mean)[grow * 32 + cq]
                         : ((const float4*)feat)[grow * 32 + cq];
        }
        *(float4*)&sA[r * SAS + ((q < 32) ? 0 : 128) + (cq << 2)] = v;
    }
    __syncthreads();

    int tx = tid & 15;   // col group: cols tx*8 .. tx*8+7
    int ty = tid >> 4;   // row group: rows ty*4 .. ty*4+3

    // accumulators: 4 rows x 4 f32x2 pairs (= 8 cols)
    uint64_t acc2[4][4];
    #pragma unroll
    for (int r = 0; r < 4; r++)
        #pragma unroll
        for (int c = 0; c < 4; c++) acc2[r][c] = 0ull;

    const float* pA = &sA[ty * 4 * SAS];
    #pragma unroll 2
    for (int k = 0; k < 2 * D; k += 4) {
        // one broadcast LDS.128 per row covers 4 k-values
        float4 a0 = *(const float4*)&pA[k];
        float4 a1 = *(const float4*)&pA[SAS + k];
        float4 a2 = *(const float4*)&pA[2 * SAS + k];
        float4 a3 = *(const float4*)&pA[3 * SAS + k];
        float a0v[4] = {a0.x, a0.y, a0.z, a0.w};
        float a1v[4] = {a1.x, a1.y, a1.z, a1.w};
        float a2v[4] = {a2.x, a2.y, a2.z, a2.w};
        float a3v[4] = {a3.x, a3.y, a3.z, a3.w};
        #pragma unroll
        for (int kk = 0; kk < 4; kk++) {
            const float* wp = &sW[(k + kk) * SWS + tx * 8];
            float4 w0 = *(const float4*)wp;
            float4 w1 = *(const float4*)(wp + 4);
            uint64_t wv2[4], av2[4];
            asm("mov.b64 %0, {%1,%2};" : "=l"(wv2[0]) : "f"(w0.x), "f"(w0.y));
            asm("mov.b64 %0, {%1,%2};" : "=l"(wv2[1]) : "f"(w0.z), "f"(w0.w));
            asm("mov.b64 %0, {%1,%2};" : "=l"(wv2[2]) : "f"(w1.x), "f"(w1.y));
            asm("mov.b64 %0, {%1,%2};" : "=l"(wv2[3]) : "f"(w1.z), "f"(w1.w));
            asm("mov.b64 %0, {%1,%1};" : "=l"(av2[0]) : "f"(a0v[kk]));
            asm("mov.b64 %0, {%1,%1};" : "=l"(av2[1]) : "f"(a1v[kk]));
            asm("mov.b64 %0, {%1,%1};" : "=l"(av2[2]) : "f"(a2v[kk]));
            asm("mov.b64 %0, {%1,%1};" : "=l"(av2[3]) : "f"(a3v[kk]));
            #pragma unroll
            for (int r = 0; r < 4; r++)
                #pragma unroll
                for (int c = 0; c < 4; c++)
                    asm("fma.rn.f32x2 %0, %1, %2, %0;"
                        : "+l"(acc2[r][c]) : "l"(av2[r]), "l"(wv2[c]));
        }
    }

    // unpack, bias, relu, store
    float b[8];
    #pragma unroll
    for (int c = 0; c < 8; c++) b[c] = bl[tx * 8 + c];

    #pragma unroll
    for (int r = 0; r < 4; r++) {
        int grow = row0 + ty * 4 + r;
        if (grow < NN) {
            float acc[8];
            #pragma unroll
            for (int c = 0; c < 4; c++)
                asm("mov.b64 {%0,%1}, %2;"
                    : "=f"(acc[2 * c]), "=f"(acc[2 * c + 1]) : "l"(acc2[r][c]));
            float4 o0, o1;
            o0.x = fmaxf(acc[0] + b[0], 0.f);
            o0.y = fmaxf(acc[1] + b[1], 0.f);
            o0.z = fmaxf(acc[2] + b[2], 0.f);
            o0.w = fmaxf(acc[3] + b[3], 0.f);
            o1.x = fmaxf(acc[4] + b[4], 0.f);
            o1.y = fmaxf(acc[5] + b[5], 0.f);
            o1.z = fmaxf(acc[6] + b[6], 0.f);
            o1.w = fmaxf(acc[7] + b[7], 0.f);
            *(float4*)&out[grow * D + tx * 8] = o0;
            *(float4*)&out[grow * D + tx * 8 + 4] = o1;
        }
    }
}

// ---------------- launch -------------------------------------------------------
extern "C" void kernel_launch(void* const* d_in, const int* in_sizes, int n_in,
                              void* d_out, int out_size) {
    const float* x  = (const float*)d_in[0];
    const int*   ei = (const int*)d_in[1];   // dtype resolved on-device (g_is64)
    const float* Wl1 = (const float*)d_in[2];
    const float* bl1 = (const float*)d_in[3];
    const float* Wr1 = (const float*)d_in[4];
    const float* Wl2 = (const float*)d_in[5];
    const float* bl2 = (const float*)d_in[6];
    const float* Wr2 = (const float*)d_in[7];
    const float* Wl3 = (const float*)d_in[8];
    const float* bl3 = (const float*)d_in[9];
    const float* Wr3 = (const float*)d_in[10];
    float* out = (float*)d_out;

    cudaFuncSetAttribute(k_gemm, cudaFuncAttributeMaxDynamicSharedMemorySize, GEMM_SMEM);

    const int nb = (NN + 511) / 512;
    const int eb = (NE + 255) / 256;
    const int gemm_blocks = (NN + TR - 1) / TR;
    const int aggr_blocks = (NN * 32 + 255) / 256;

    // CSR build (rebuilt each call for determinism rules)
    k_detect<<<1, 256>>>(ei);
    k_zero_deg<<<(NN + 255) / 256, 256>>>();
    k_deg<<<eb, 256>>>(ei);
    k_scan1<<<nb, 512>>>();
    k_scan2<<<1, 32>>>(nb);
    k_scan3<<<nb, 512>>>();
    k_fill<<<eb, 256>>>(ei);

    // layer 1: feat=x -> g_hA
    k_aggr<<<aggr_blocks, 256>>>(x, 0);
    k_gemm<<<gemm_blocks, 256, GEMM_SMEM>>>(x, Wl1, bl1, Wr1, out, 0);
    // layer 2: feat=g_hA -> g_hB
    k_aggr<<<aggr_blocks, 256>>>(x, 1);
    k_gemm<<<gemm_blocks, 256, GEMM_SMEM>>>(x, Wl2, bl2, Wr2, out, 1);
    // layer 3: feat=g_hB -> out
    k_aggr<<<aggr_blocks, 256>>>(x, 2);
    k_gemm<<<gemm_blocks, 256, GEMM_SMEM>>>(x, Wl3, bl3, Wr3, out, 2);
}